// round 6
// baseline (speedup 1.0000x reference)
#include <cuda_runtime.h>
#include <cstdint>

#define HIDDEN 1024
#define HEADS  16
#define DKH    64
#define BB     2
#define NN     2048
#define ROWS   (BB*NN)

__device__ float g_Q[ROWS * HIDDEN];
__device__ float g_K[ROWS * HIDDEN];
__device__ float g_V[ROWS * HIDDEN];
__device__ float g_C[ROWS * HIDDEN];

__device__ __forceinline__ uint32_t f2tf(float x) {
    uint32_t u; asm("cvt.rna.tf32.f32 %0, %1;" : "=r"(u) : "f"(x)); return u;
}
__device__ __forceinline__ uint32_t pk(float a, float b) {
    uint32_t r; asm("cvt.rn.bf16x2.f32 %0, %1, %2;" : "=r"(r) : "f"(b), "f"(a)); return r;
}
__device__ __forceinline__ float blo(uint32_t u) { return __uint_as_float(u << 16); }
__device__ __forceinline__ float bhi(uint32_t u) { return __uint_as_float(u & 0xffff0000u); }
__device__ __forceinline__ void sp(float f0, float f1, uint32_t& h, uint32_t& l) {
    h = pk(f0, f1);
    l = pk(f0 - blo(h), f1 - bhi(h));
}
__device__ __forceinline__ void mma8(float* d, uint32_t a0, uint32_t a1,
    uint32_t a2, uint32_t a3, uint32_t b0, uint32_t b1) {
    asm volatile("mma.sync.aligned.m16n8k8.row.col.f32.tf32.tf32.f32 "
        "{%0,%1,%2,%3},{%4,%5,%6,%7},{%8,%9},{%0,%1,%2,%3};"
        : "+f"(d[0]), "+f"(d[1]), "+f"(d[2]), "+f"(d[3])
        : "r"(a0), "r"(a1), "r"(a2), "r"(a3), "r"(b0), "r"(b1));
}
__device__ __forceinline__ void mma16(float* d, uint32_t a0, uint32_t a1,
    uint32_t a2, uint32_t a3, uint32_t b0, uint32_t b1) {
    asm volatile("mma.sync.aligned.m16n8k16.row.col.f32.bf16.bf16.f32 "
        "{%0,%1,%2,%3},{%4,%5,%6,%7},{%8,%9},{%0,%1,%2,%3};"
        : "+f"(d[0]), "+f"(d[1]), "+f"(d[2]), "+f"(d[3])
        : "r"(a0), "r"(a1), "r"(a2), "r"(a3), "r"(b0), "r"(b1));
}

// ---------------------------------------------------------------------------
// bf16x3 GEMM, double-buffered smem, 1 sync per k-step. 2 CTA/SM.
// ---------------------------------------------------------------------------
__global__ void __launch_bounds__(256, 2) gemm_bf3_kernel(
    const float* __restrict__ A, const float* __restrict__ W,
    const float* __restrict__ bias, float* __restrict__ C,
    int M, int N, int K)
{
    __shared__ uint32_t Ah[2][8][136], Al[2][8][136], Wh[2][8][136], Wl[2][8][136];
    const int tid = threadIdx.x, lane = tid & 31, wid = tid >> 5;
    const int g = lane >> 2, t = lane & 3;
    const int wm = (wid & 3) * 32, wn = (wid >> 2) * 64;
    const float* Ab = A + (size_t)blockIdx.y * 128 * K;
    const float* Wb = W + (size_t)blockIdx.x * 128;

    float acc[2][8][4];
#pragma unroll
    for (int mi = 0; mi < 2; mi++)
#pragma unroll
        for (int n = 0; n < 8; n++)
#pragma unroll
            for (int j = 0; j < 4; j++) acc[mi][n][j] = 0.f;

    const int arow = tid >> 2, ac4 = tid & 3;
    const int kp = tid >> 5, c4 = tid & 31;

    float4 ra0, ra1, rw0, rw1;
#define G_LOAD(k0) do { \
    ra0 = *(const float4*)(Ab + (size_t)arow * K + (k0) + ac4 * 4); \
    ra1 = *(const float4*)(Ab + (size_t)(arow + 64) * K + (k0) + ac4 * 4); \
    rw0 = *(const float4*)(Wb + (size_t)((k0) + 2 * kp) * N + c4 * 4); \
    rw1 = *(const float4*)(Wb + (size_t)((k0) + 2 * kp + 1) * N + c4 * 4); \
} while (0)
#define G_STS(pb) do { \
    uint32_t h_, l_; \
    sp(ra0.x, ra0.y, h_, l_); Ah[pb][2*ac4][arow] = h_;      Al[pb][2*ac4][arow] = l_; \
    sp(ra0.z, ra0.w, h_, l_); Ah[pb][2*ac4+1][arow] = h_;    Al[pb][2*ac4+1][arow] = l_; \
    sp(ra1.x, ra1.y, h_, l_); Ah[pb][2*ac4][arow+64] = h_;   Al[pb][2*ac4][arow+64] = l_; \
    sp(ra1.z, ra1.w, h_, l_); Ah[pb][2*ac4+1][arow+64] = h_; Al[pb][2*ac4+1][arow+64] = l_; \
    uint4 vh_, vl_; \
    sp(rw0.x, rw1.x, vh_.x, vl_.x); sp(rw0.y, rw1.y, vh_.y, vl_.y); \
    sp(rw0.z, rw1.z, vh_.z, vl_.z); sp(rw0.w, rw1.w, vh_.w, vl_.w); \
    *(uint4*)&Wh[pb][kp][c4 * 4] = vh_; \
    *(uint4*)&Wl[pb][kp][c4 * 4] = vl_; \
} while (0)

    G_LOAD(0);
    G_STS(0);
    __syncthreads();
    int p = 0;

    for (int k0 = 0; k0 < K; k0 += 16) {
        if (k0 + 16 < K) G_LOAD(k0 + 16);

        uint32_t af[2][8];
#pragma unroll
        for (int mi = 0; mi < 2; mi++) {
            int mb = wm + mi * 16;
            af[mi][0] = Ah[p][t][mb+g];   af[mi][1] = Ah[p][t][mb+g+8];
            af[mi][2] = Ah[p][t+4][mb+g]; af[mi][3] = Ah[p][t+4][mb+g+8];
            af[mi][4] = Al[p][t][mb+g];   af[mi][5] = Al[p][t][mb+g+8];
            af[mi][6] = Al[p][t+4][mb+g]; af[mi][7] = Al[p][t+4][mb+g+8];
        }
#pragma unroll
        for (int n = 0; n < 8; n++) {
            uint32_t b0h = Wh[p][t][wn+n*8+g], b1h = Wh[p][t+4][wn+n*8+g];
            uint32_t b0l = Wl[p][t][wn+n*8+g], b1l = Wl[p][t+4][wn+n*8+g];
#pragma unroll
            for (int mi = 0; mi < 2; mi++) {
                mma16(acc[mi][n], af[mi][0], af[mi][1], af[mi][2], af[mi][3], b0h, b1h);
                mma16(acc[mi][n], af[mi][4], af[mi][5], af[mi][6], af[mi][7], b0h, b1h);
                mma16(acc[mi][n], af[mi][0], af[mi][1], af[mi][2], af[mi][3], b0l, b1l);
            }
        }
        if (k0 + 16 < K) G_STS(p ^ 1);
        __syncthreads();
        p ^= 1;
    }

#pragma unroll
    for (int mi = 0; mi < 2; mi++) {
        int row0 = blockIdx.y * 128 + wm + mi * 16 + g;
#pragma unroll
        for (int n = 0; n < 8; n++) {
            int col = blockIdx.x * 128 + wn + n * 8 + 2 * t;
            float2 bv = *(const float2*)(bias + col);
            *(float2*)(C + (size_t)row0 * N + col) =
                make_float2(acc[mi][n][0] + bv.x, acc[mi][n][1] + bv.y);
            *(float2*)(C + (size_t)(row0 + 8) * N + col) =
                make_float2(acc[mi][n][2] + bv.x, acc[mi][n][3] + bv.y);
        }
    }
}

// ---------------------------------------------------------------------------
// Flash, double-buffered + register prefetch + exp2 domain.
// Br=128, Bc=64, 256 thr. Layouts identical to round-5 (proven).
// ---------------------------------------------------------------------------
#define KSZ (64 * 68)
#define VSZ (32 * 72)
#define BUFU32 (KSZ + 2 * VSZ)               // 8960 u32 = 35840 B
#define FSM_BYTES (2 * BUFU32 * 4)           // 71680 B

__global__ void __launch_bounds__(256) flash_kernel(
    const float* __restrict__ bias, const float* __restrict__ mask,
    float* __restrict__ ctx)
{
    extern __shared__ uint32_t smf[];
    const int tid = threadIdx.x, lane = tid & 31, wid = tid >> 5;
    const int g = lane >> 2, t = lane & 3;
    const int wrow = wid * 16;
    const int h = blockIdx.x, q0 = blockIdx.y * 128, b = blockIdx.z;

    const float* Qg = g_Q + ((size_t)b * NN + q0) * HIDDEN + h * DKH;
    const float* Kg = g_K + (size_t)b * NN * HIDDEN + h * DKH;
    const float* Vg = g_V + (size_t)b * NN * HIDDEN + h * DKH;

    const float L2E = 1.44269504088896340736f;
    const float QSC = 0.125f * L2E;          // scale * log2(e), folded into Q

    uint32_t qa[8][4];
#pragma unroll
    for (int kb = 0; kb < 8; kb++) {
        qa[kb][0] = f2tf(__ldg(Qg + (size_t)(wrow+g)  *HIDDEN + kb*8 + t)   * QSC);
        qa[kb][1] = f2tf(__ldg(Qg + (size_t)(wrow+g+8)*HIDDEN + kb*8 + t)   * QSC);
        qa[kb][2] = f2tf(__ldg(Qg + (size_t)(wrow+g)  *HIDDEN + kb*8 + t+4) * QSC);
        qa[kb][3] = f2tf(__ldg(Qg + (size_t)(wrow+g+8)*HIDDEN + kb*8 + t+4) * QSC);
    }

    float Oa[8][4];
#pragma unroll
    for (int n = 0; n < 8; n++)
#pragma unroll
        for (int j = 0; j < 4; j++) Oa[n][j] = 0.f;
    float m0 = -1e30f, m1 = -1e30f, l0 = 0.f, l1 = 0.f;

    const float* biasB = bias + ((size_t)b * NN + q0 + wrow) * NN;
    const float* maskB = mask + ((size_t)b * NN + q0 + wrow) * NN;

    float4 pkv[4];
    float2 pva[4], pvb[4];
#define F_LOADKV(k0) do { \
    _Pragma("unroll") for (int i = 0; i < 4; i++) { \
        int li = tid + i * 256, r = li >> 4, cc = li & 15; \
        pkv[i] = *(const float4*)(Kg + (size_t)((k0) + r) * HIDDEN + cc * 4); } \
    _Pragma("unroll") for (int i = 0; i < 4; i++) { \
        int li = tid + i * 256, rp = li >> 5, c2 = li & 31; \
        pva[i] = *(const float2*)(Vg + (size_t)((k0) + 2*rp)   * HIDDEN + c2 * 2); \
        pvb[i] = *(const float2*)(Vg + (size_t)((k0) + 2*rp+1) * HIDDEN + c2 * 2); } \
} while (0)
#define F_STSKV(base) do { \
    uint32_t* Ksb = (base); uint32_t* Vhb = (base) + KSZ; uint32_t* Vlb = (base) + KSZ + VSZ; \
    _Pragma("unroll") for (int i = 0; i < 4; i++) { \
        int li = tid + i * 256, r = li >> 4, cc = li & 15; \
        uint4 u_; u_.x = f2tf(pkv[i].x); u_.y = f2tf(pkv[i].y); \
        u_.z = f2tf(pkv[i].z); u_.w = f2tf(pkv[i].w); \
        *(uint4*)&Ksb[r * 68 + cc * 4] = u_; } \
    _Pragma("unroll") for (int i = 0; i < 4; i++) { \
        int li = tid + i * 256, rp = li >> 5, c2 = li & 31; \
        uint2 uh_, ul_; \
        sp(pva[i].x, pvb[i].x, uh_.x, ul_.x); \
        sp(pva[i].y, pvb[i].y, uh_.y, ul_.y); \
        *(uint2*)&Vhb[rp * 72 + c2 * 2] = uh_; \
        *(uint2*)&Vlb[rp * 72 + c2 * 2] = ul_; } \
} while (0)

    F_LOADKV(0);
    F_STSKV(smf);
    __syncthreads();
    int p = 0;

    for (int kt = 0; kt < NN / 64; kt++) {
        const int k0 = kt * 64;
        uint32_t* Ksb = smf + p * BUFU32;
        uint32_t* Vhb = Ksb + KSZ;
        uint32_t* Vlb = Ksb + KSZ + VSZ;

        if (kt + 1 < NN / 64) F_LOADKV(k0 + 64);   // LDGs in flight under compute

        // bias/mask prefetch (issued before mma, consumed after)
        const float* b0p = biasB + (size_t)g * NN + k0;
        const float* b1p = biasB + (size_t)(g+8) * NN + k0;
        const float* m0p = maskB + (size_t)g * NN + k0;
        const float* m1p = maskB + (size_t)(g+8) * NN + k0;
        float2 ub[8], um[8], wb[8], wm[8];
#pragma unroll
        for (int n = 0; n < 8; n++) {
            ub[n] = __ldg((const float2*)(b0p + n*8 + 2*t));
            um[n] = __ldg((const float2*)(m0p + n*8 + 2*t));
            wb[n] = __ldg((const float2*)(b1p + n*8 + 2*t));
            wm[n] = __ldg((const float2*)(m1p + n*8 + 2*t));
        }

        // S' = (Q*scale*log2e) @ K^T
        float sacc[8][4];
#pragma unroll
        for (int n = 0; n < 8; n++)
#pragma unroll
            for (int j = 0; j < 4; j++) sacc[n][j] = 0.f;
#pragma unroll
        for (int kb = 0; kb < 8; kb++)
#pragma unroll
            for (int n = 0; n < 8; n++) {
                uint32_t b0 = Ksb[(n*8+g) * 68 + kb*8 + t];
                uint32_t b1 = Ksb[(n*8+g) * 68 + kb*8 + t + 4];
                mma8(sacc[n], qa[kb][0], qa[kb][1], qa[kb][2], qa[kb][3], b0, b1);
            }

        // + (bias+mask)*log2e, online softmax in exp2 domain
        float mx0 = -1e30f, mx1 = -1e30f;
#pragma unroll
        for (int n = 0; n < 8; n++) {
            sacc[n][0] = fmaf(ub[n].x, L2E, sacc[n][0]);
            sacc[n][0] = fmaf(um[n].x, L2E, sacc[n][0]);
            sacc[n][1] = fmaf(ub[n].y, L2E, sacc[n][1]);
            sacc[n][1] = fmaf(um[n].y, L2E, sacc[n][1]);
            sacc[n][2] = fmaf(wb[n].x, L2E, sacc[n][2]);
            sacc[n][2] = fmaf(wm[n].x, L2E, sacc[n][2]);
            sacc[n][3] = fmaf(wb[n].y, L2E, sacc[n][3]);
            sacc[n][3] = fmaf(wm[n].y, L2E, sacc[n][3]);
            mx0 = fmaxf(mx0, fmaxf(sacc[n][0], sacc[n][1]));
            mx1 = fmaxf(mx1, fmaxf(sacc[n][2], sacc[n][3]));
        }
        mx0 = fmaxf(mx0, __shfl_xor_sync(~0u, mx0, 1));
        mx0 = fmaxf(mx0, __shfl_xor_sync(~0u, mx0, 2));
        mx1 = fmaxf(mx1, __shfl_xor_sync(~0u, mx1, 1));
        mx1 = fmaxf(mx1, __shfl_xor_sync(~0u, mx1, 2));
        float mn0 = fmaxf(m0, mx0), mn1 = fmaxf(m1, mx1);
        float c0 = exp2f(m0 - mn0), c1 = exp2f(m1 - mn1);
        float rs0 = 0.f, rs1 = 0.f;
#pragma unroll
        for (int n = 0; n < 8; n++) {
            sacc[n][0] = exp2f(sacc[n][0] - mn0);
            sacc[n][1] = exp2f(sacc[n][1] - mn0);
            sacc[n][2] = exp2f(sacc[n][2] - mn1);
            sacc[n][3] = exp2f(sacc[n][3] - mn1);
            rs0 += sacc[n][0] + sacc[n][1];
            rs1 += sacc[n][2] + sacc[n][3];
        }
        rs0 += __shfl_xor_sync(~0u, rs0, 1); rs0 += __shfl_xor_sync(~0u, rs0, 2);
        rs1 += __shfl_xor_sync(~0u, rs1, 1); rs1 += __shfl_xor_sync(~0u, rs1, 2);
        l0 = l0 * c0 + rs0; l1 = l1 * c1 + rs1;
        m0 = mn0; m1 = mn1;
#pragma unroll
        for (int n = 0; n < 8; n++) {
            Oa[n][0] *= c0; Oa[n][1] *= c0;
            Oa[n][2] *= c1; Oa[n][3] *= c1;
        }

        // O += P @ V (bf16x3, P in regs)
#pragma unroll
        for (int kb = 0; kb < 4; kb++) {
            uint32_t a0h, a0l, a1h, a1l, a2h, a2l, a3h, a3l;
            sp(sacc[2*kb][0],   sacc[2*kb][1],   a0h, a0l);
            sp(sacc[2*kb][2],   sacc[2*kb][3],   a1h, a1l);
            sp(sacc[2*kb+1][0], sacc[2*kb+1][1], a2h, a2l);
            sp(sacc[2*kb+1][2], sacc[2*kb+1][3], a3h, a3l);
#pragma unroll
            for (int n = 0; n < 8; n++) {
                uint32_t b0h = Vhb[(kb*8+t)   * 72 + n*8 + g];
                uint32_t b1h = Vhb[(kb*8+t+4) * 72 + n*8 + g];
                uint32_t b0l = Vlb[(kb*8+t)   * 72 + n*8 + g];
                uint32_t b1l = Vlb[(kb*8+t+4) * 72 + n*8 + g];
                mma16(Oa[n], a0h, a1h, a2h, a3h, b0h, b1h);
                mma16(Oa[n], a0l, a1l, a2l, a3l, b0h, b1h);
                mma16(Oa[n], a0h, a1h, a2h, a3h, b0l, b1l);
            }
        }

        if (kt + 1 < NN / 64) F_STSKV(smf + (p ^ 1) * BUFU32);
        __syncthreads();
        p ^= 1;
    }

    float inv0 = 1.f / l0, inv1 = 1.f / l1;
    float* o0 = ctx + ((size_t)b * NN + q0 + wrow + g) * HIDDEN + h * DKH;
    float* o1 = o0 + (size_t)8 * HIDDEN;
#pragma unroll
    for (int n = 0; n < 8; n++) {
        *(float2*)&o0[n*8 + 2*t] = make_float2(Oa[n][0]*inv0, Oa[n][1]*inv0);
        *(float2*)&o1[n*8 + 2*t] = make_float2(Oa[n][2]*inv1, Oa[n][3]*inv1);
    }
}

extern "C" void kernel_launch(void* const* d_in, const int* in_sizes, int n_in,
                              void* d_out, int out_size)
{
    const float* q    = (const float*)d_in[0];
    const float* k    = (const float*)d_in[1];
    const float* v    = (const float*)d_in[2];
    const float* abia = (const float*)d_in[3];
    const float* amask= (const float*)d_in[4];
    const float* Wq   = (const float*)d_in[5];
    const float* bq   = (const float*)d_in[6];
    const float* Wk   = (const float*)d_in[7];
    const float* bk   = (const float*)d_in[8];
    const float* Wv   = (const float*)d_in[9];
    const float* bv   = (const float*)d_in[10];
    const float* Wo   = (const float*)d_in[11];
    const float* bo   = (const float*)d_in[12];
    float* out = (float*)d_out;

    float *Qp, *Kp, *Vp, *Cp;
    cudaGetSymbolAddress((void**)&Qp, g_Q);
    cudaGetSymbolAddress((void**)&Kp, g_K);
    cudaGetSymbolAddress((void**)&Vp, g_V);
    cudaGetSymbolAddress((void**)&Cp, g_C);

    cudaFuncSetAttribute(flash_kernel,
                         cudaFuncAttributeMaxDynamicSharedMemorySize, FSM_BYTES);

    dim3 gb(HIDDEN / 128, ROWS / 128);     // (8, 32)
    gemm_bf3_kernel<<<gb, 256>>>(q, Wq, bq, Qp, ROWS, HIDDEN, HIDDEN);
    gemm_bf3_kernel<<<gb, 256>>>(k, Wk, bk, Kp, ROWS, HIDDEN, HIDDEN);
    gemm_bf3_kernel<<<gb, 256>>>(v, Wv, bv, Vp, ROWS, HIDDEN, HIDDEN);

    dim3 gf(HEADS, NN / 128, BB);          // (16, 16, 2)
    flash_kernel<<<gf, 256, FSM_BYTES>>>(abia, amask, Cp);

    gemm_bf3_kernel<<<gb, 256>>>(Cp, Wo, bo, out, ROWS, HIDDEN, HIDDEN);
}